// round 2
// baseline (speedup 1.0000x reference)
#include <cuda_runtime.h>
#include <cuda_bf16.h>
#include <mma.h>
#include <math_constants.h>

using namespace nvcuda;

// Problem constants
#define DMODEL 1024
#define NHEADS 16
#define DHEAD  64
#define NBATCH 2
#define SQ     2048
#define SK     2048
#define MROWS  (NBATCH * SQ)   // 4096

// ---------------------------------------------------------------------------
// Scratch (device globals: no allocation allowed)
// ---------------------------------------------------------------------------
__device__ float g_qh[(size_t)NBATCH * NHEADS * SQ * DHEAD];   // 16 MB, [b,h,q,d]
__device__ float g_kh[(size_t)NBATCH * NHEADS * SK * DHEAD];   // 16 MB
__device__ float g_vh[(size_t)NBATCH * NHEADS * SK * DHEAD];   // 16 MB
__device__ float g_attn[(size_t)NBATCH * SQ * DMODEL];          // 16 MB, [b,q, h*64+d]

// ---------------------------------------------------------------------------
// TF32 wmma GEMM: C[4096,1024] = A[4096,1024] @ W[1024,1024] + bias
// DST: 0 -> g_qh (head-major), 1 -> g_kh, 2 -> g_vh, 3 -> plain row-major `out`
// For DST==3 the A operand is g_attn (param `A` ignored).
// ---------------------------------------------------------------------------
template<int DST>
__global__ __launch_bounds__(256)
void gemm_tf32_kernel(const float* __restrict__ A,
                      const float* __restrict__ W,
                      const float* __restrict__ bias,
                      float* __restrict__ out)
{
    constexpr int BM = 128, BN = 128, BK = 32;
    __shared__ float As[BM][36];     // ld 36 (144B, 16B-multiple)
    __shared__ float Bs[BK][132];    // ld 132 (528B, 16B-multiple)
    __shared__ float stage[8][256];  // per-warp 16x16 epilogue staging

    const float* Ap = (DST == 3) ? g_attn : A;

    const int tid    = threadIdx.x;
    const int wid    = tid >> 5;
    const int lane   = tid & 31;
    const int warp_m = wid >> 1;   // 0..3
    const int warp_n = wid & 1;    // 0..1
    const int m0 = blockIdx.y * BM;
    const int n0 = blockIdx.x * BN;

    wmma::fragment<wmma::accumulator, 16, 16, 8, float> acc[2][4];
#pragma unroll
    for (int i = 0; i < 2; i++)
#pragma unroll
        for (int j = 0; j < 4; j++)
            wmma::fill_fragment(acc[i][j], 0.0f);

    for (int k0 = 0; k0 < DMODEL; k0 += BK) {
        // Load A tile 128x32 (1024 float4s, 4 per thread)
#pragma unroll
        for (int i = 0; i < 4; i++) {
            int idx = tid + i * 256;
            int r = idx >> 3, c4 = idx & 7;
            float4 v = *(const float4*)(Ap + (size_t)(m0 + r) * DMODEL + k0 + c4 * 4);
            *(float4*)(&As[r][c4 * 4]) = v;
        }
        // Load W tile 32x128
#pragma unroll
        for (int i = 0; i < 4; i++) {
            int idx = tid + i * 256;
            int r = idx >> 5, c4 = idx & 31;
            float4 v = *(const float4*)(W + (size_t)(k0 + r) * DMODEL + n0 + c4 * 4);
            *(float4*)(&Bs[r][c4 * 4]) = v;
        }
        __syncthreads();

#pragma unroll
        for (int kf = 0; kf < 4; kf++) {
            wmma::fragment<wmma::matrix_a, 16, 16, 8, wmma::precision::tf32, wmma::row_major> a[2];
            wmma::fragment<wmma::matrix_b, 16, 16, 8, wmma::precision::tf32, wmma::row_major> b[4];
#pragma unroll
            for (int i = 0; i < 2; i++) {
                wmma::load_matrix_sync(a[i], &As[warp_m * 32 + i * 16][kf * 8], 36);
#pragma unroll
                for (int t = 0; t < a[i].num_elements; t++)
                    a[i].x[t] = wmma::__float_to_tf32(a[i].x[t]);
            }
#pragma unroll
            for (int j = 0; j < 4; j++) {
                wmma::load_matrix_sync(b[j], &Bs[kf * 8][warp_n * 64 + j * 16], 132);
#pragma unroll
                for (int t = 0; t < b[j].num_elements; t++)
                    b[j].x[t] = wmma::__float_to_tf32(b[j].x[t]);
            }
#pragma unroll
            for (int i = 0; i < 2; i++)
#pragma unroll
                for (int j = 0; j < 4; j++)
                    wmma::mma_sync(acc[i][j], a[i], b[j], acc[i][j]);
        }
        __syncthreads();
    }

    // Epilogue: stage each 16x16 frag in smem, add bias, scatter to output
#pragma unroll
    for (int i = 0; i < 2; i++) {
#pragma unroll
        for (int j = 0; j < 4; j++) {
            wmma::store_matrix_sync(&stage[wid][0], acc[i][j], 16, wmma::mem_row_major);
            __syncwarp();
            int grow0 = m0 + warp_m * 32 + i * 16;
            int gcol0 = n0 + warp_n * 64 + j * 16;
#pragma unroll
            for (int t = lane; t < 256; t += 32) {
                int r = t >> 4, c = t & 15;
                int grow = grow0 + r;
                int gcol = gcol0 + c;
                float v = stage[wid][t] + bias[gcol];
                if (DST <= 2) {
                    // head-major: [b, h, row, d]
                    int b_  = grow >> 11;          // /2048
                    int qr  = grow & 2047;
                    int h_  = gcol >> 6;           // /64
                    int d_  = gcol & 63;
                    size_t addr = (((size_t)(b_ * NHEADS + h_) * SQ) + qr) * DHEAD + d_;
                    if (DST == 0) g_qh[addr] = v;
                    else if (DST == 1) g_kh[addr] = v;
                    else g_vh[addr] = v;
                } else {
                    out[(size_t)grow * DMODEL + gcol] = v;
                }
            }
            __syncwarp();
        }
    }
}

// ---------------------------------------------------------------------------
// Flash attention: one CTA per (b, h, 64-query tile). TF32 wmma for QK^T / PV,
// online softmax in fp32. Writes merged layout [b, q, h*64+d] into g_attn.
// ---------------------------------------------------------------------------
#define FL_LD 68   // 68*4 = 272 bytes = 17*16, 16B-multiple

__global__ __launch_bounds__(128)
void flash_attn_kernel()
{
    extern __shared__ float sm[];
    float* Qs = sm;                 // 64 x FL_LD
    float* Ks = Qs + 64 * FL_LD;
    float* Vs = Ks + 64 * FL_LD;
    float* Ss = Vs + 64 * FL_LD;
    float* Os = Ss + 64 * FL_LD;

    const int q0  = blockIdx.x * 64;
    const int h   = blockIdx.y;
    const int b   = blockIdx.z;
    const int tid = threadIdx.x;
    const int wid = tid >> 5;
    const int lane = tid & 31;

    const float* Qg = g_qh + (((size_t)(b * NHEADS + h) * SQ) + q0) * DHEAD;
    const float* Kg = g_kh + ((size_t)(b * NHEADS + h) * SK) * DHEAD;
    const float* Vg = g_vh + ((size_t)(b * NHEADS + h) * SK) * DHEAD;

    // Load Q tile + zero O accumulator
    for (int i = tid; i < 64 * 16; i += 128) {
        int r = i >> 4, c4 = i & 15;
        *(float4*)(Qs + r * FL_LD + c4 * 4) = *(const float4*)(Qg + (size_t)r * DHEAD + c4 * 4);
        float4 z = make_float4(0.f, 0.f, 0.f, 0.f);
        *(float4*)(Os + r * FL_LD + c4 * 4) = z;
    }

    const int rloc = lane >> 1;         // 0..15 (row within warp strip)
    const int half = lane & 1;          // which 32-col half
    const int row  = wid * 16 + rloc;   // 0..63
    float* Srow = Ss + row * FL_LD + half * 32;
    float* Orow = Os + row * FL_LD + half * 32;

    float m_i = -CUDART_INF_F;
    float l_i = 0.0f;

    __syncthreads();

    for (int j = 0; j < SK; j += 64) {
        // Load K,V tiles (64x64 each)
        for (int i = tid; i < 64 * 16; i += 128) {
            int r = i >> 4, c4 = i & 15;
            *(float4*)(Ks + r * FL_LD + c4 * 4) =
                *(const float4*)(Kg + (size_t)(j + r) * DHEAD + c4 * 4);
            *(float4*)(Vs + r * FL_LD + c4 * 4) =
                *(const float4*)(Vg + (size_t)(j + r) * DHEAD + c4 * 4);
        }
        __syncthreads();

        // S = (Q K^T) * scale — warp computes its 16-row strip, all 64 cols
        {
            const int r0 = wid * 16;
#pragma unroll
            for (int n0 = 0; n0 < 64; n0 += 16) {
                wmma::fragment<wmma::accumulator, 16, 16, 8, float> c;
                wmma::fill_fragment(c, 0.0f);
#pragma unroll
                for (int k0 = 0; k0 < 64; k0 += 8) {
                    wmma::fragment<wmma::matrix_a, 16, 16, 8, wmma::precision::tf32, wmma::row_major> a;
                    wmma::fragment<wmma::matrix_b, 16, 16, 8, wmma::precision::tf32, wmma::col_major> bf;
                    wmma::load_matrix_sync(a, Qs + r0 * FL_LD + k0, FL_LD);
                    // K^T via col_major view of row-major K tile
                    wmma::load_matrix_sync(bf, Ks + n0 * FL_LD + k0, FL_LD);
#pragma unroll
                    for (int t = 0; t < a.num_elements; t++) a.x[t] = wmma::__float_to_tf32(a.x[t]);
#pragma unroll
                    for (int t = 0; t < bf.num_elements; t++) bf.x[t] = wmma::__float_to_tf32(bf.x[t]);
                    wmma::mma_sync(c, a, bf, c);
                }
#pragma unroll
                for (int t = 0; t < c.num_elements; t++) c.x[t] *= 0.125f;  // 1/sqrt(64)
                wmma::store_matrix_sync(Ss + r0 * FL_LD + n0, c, FL_LD, wmma::mem_row_major);
            }
        }
        __syncwarp();

        // Online softmax over this warp's 16 rows (2 lanes per row)
        {
            float sv[32];
            float mx = -CUDART_INF_F;
#pragma unroll
            for (int i = 0; i < 32; i++) { sv[i] = Srow[i]; mx = fmaxf(mx, sv[i]); }
            mx = fmaxf(mx, __shfl_xor_sync(0xffffffffu, mx, 1));
            float m_new = fmaxf(m_i, mx);
            float alpha = __expf(m_i - m_new);
            float s = 0.0f;
#pragma unroll
            for (int i = 0; i < 32; i++) {
                float p = __expf(sv[i] - m_new);
                Srow[i] = p;
                s += p;
            }
            s += __shfl_xor_sync(0xffffffffu, s, 1);
            l_i = l_i * alpha + s;
            m_i = m_new;
#pragma unroll
            for (int i = 0; i < 32; i++) Orow[i] *= alpha;
        }
        __syncwarp();

        // O += P @ V
        {
            const int r0 = wid * 16;
#pragma unroll
            for (int n0 = 0; n0 < 64; n0 += 16) {
                wmma::fragment<wmma::accumulator, 16, 16, 8, float> c;
                wmma::load_matrix_sync(c, Os + r0 * FL_LD + n0, FL_LD, wmma::mem_row_major);
#pragma unroll
                for (int k0 = 0; k0 < 64; k0 += 8) {
                    wmma::fragment<wmma::matrix_a, 16, 16, 8, wmma::precision::tf32, wmma::row_major> a;
                    wmma::fragment<wmma::matrix_b, 16, 16, 8, wmma::precision::tf32, wmma::row_major> bf;
                    wmma::load_matrix_sync(a, Ss + r0 * FL_LD + k0, FL_LD);
                    wmma::load_matrix_sync(bf, Vs + k0 * FL_LD + n0, FL_LD);
#pragma unroll
                    for (int t = 0; t < a.num_elements; t++) a.x[t] = wmma::__float_to_tf32(a.x[t]);
#pragma unroll
                    for (int t = 0; t < bf.num_elements; t++) bf.x[t] = wmma::__float_to_tf32(bf.x[t]);
                    wmma::mma_sync(c, a, bf, c);
                }
                wmma::store_matrix_sync(Os + r0 * FL_LD + n0, c, FL_LD, wmma::mem_row_major);
            }
        }
        __syncthreads();   // protect Ks/Vs/Ss reuse next iteration
    }

    // Normalize and write merged layout [b, q, h*64 + d]
    float inv_l = 1.0f / l_i;
    float* og = g_attn + ((size_t)(b * SQ + q0 + row) * DMODEL) + h * DHEAD + half * 32;
#pragma unroll
    for (int i = 0; i < 32; i++) og[i] = Orow[i] * inv_l;
}

// ---------------------------------------------------------------------------
// Launch
// ---------------------------------------------------------------------------
extern "C" void kernel_launch(void* const* d_in, const int* in_sizes, int n_in,
                              void* d_out, int out_size)
{
    const float* q  = (const float*)d_in[0];
    const float* k  = (const float*)d_in[1];
    const float* v  = (const float*)d_in[2];
    const float* Wq = (const float*)d_in[3];
    const float* bq = (const float*)d_in[4];
    const float* Wk = (const float*)d_in[5];
    const float* bk = (const float*)d_in[6];
    const float* Wv = (const float*)d_in[7];
    const float* bv = (const float*)d_in[8];
    const float* Wo = (const float*)d_in[9];
    const float* bo = (const float*)d_in[10];
    float* out = (float*)d_out;

    dim3 gblock(256);
    dim3 ggrid(DMODEL / 128, MROWS / 128);   // (8, 32)

    // Projections -> head-major scratch
    gemm_tf32_kernel<0><<<ggrid, gblock>>>(q, Wq, bq, nullptr);
    gemm_tf32_kernel<1><<<ggrid, gblock>>>(k, Wk, bk, nullptr);
    gemm_tf32_kernel<2><<<ggrid, gblock>>>(v, Wv, bv, nullptr);

    // Flash attention
    const int flash_smem = 5 * 64 * FL_LD * (int)sizeof(float);  // 87,040 B
    cudaFuncSetAttribute(flash_attn_kernel,
                         cudaFuncAttributeMaxDynamicSharedMemorySize, flash_smem);
    dim3 fgrid(SQ / 64, NHEADS, NBATCH);     // (32, 16, 2)
    flash_attn_kernel<<<fgrid, 128, flash_smem>>>();

    // Output projection (reads g_attn internally)
    gemm_tf32_kernel<3><<<ggrid, gblock>>>(nullptr, Wo, bo, out);
}

// round 4
// speedup vs baseline: 1.7855x; 1.7855x over previous
#include <cuda_runtime.h>
#include <cuda_bf16.h>
#include <mma.h>
#include <math_constants.h>
#include <cstdint>

using namespace nvcuda;

#define DMODEL 1024
#define NHEADS 16
#define DHEAD  64
#define NBATCH 2
#define SQ     2048
#define SK     2048
#define MROWS  (NBATCH * SQ)   // 4096

// ---------------------------------------------------------------------------
// Scratch (device globals: no allocation allowed)
// ---------------------------------------------------------------------------
__device__ float g_qh[(size_t)NBATCH * NHEADS * SQ * DHEAD];   // [b,h,q,d]
__device__ float g_kh[(size_t)NBATCH * NHEADS * SK * DHEAD];
__device__ float g_vh[(size_t)NBATCH * NHEADS * SK * DHEAD];
__device__ float g_attn[(size_t)NBATCH * SQ * DMODEL];          // [b,q, h*64+d]

// ---------------------------------------------------------------------------
// helpers
// ---------------------------------------------------------------------------
__device__ __forceinline__ void cp_async16(void* smem, const void* gmem) {
    uint32_t s = (uint32_t)__cvta_generic_to_shared(smem);
    asm volatile("cp.async.cg.shared.global [%0], [%1], 16;\n" :: "r"(s), "l"(gmem));
}
__device__ __forceinline__ void cp_commit() { asm volatile("cp.async.commit_group;\n"); }
template<int N> __device__ __forceinline__ void cp_wait() {
    asm volatile("cp.async.wait_group %0;\n" :: "n"(N));
}
__device__ __forceinline__ uint32_t f2tf32(float f) {
    uint32_t r; asm("cvt.rna.tf32.f32 %0, %1;" : "=r"(r) : "f"(f)); return r;
}
__device__ __forceinline__ void mma_tf32(float c[4], const uint32_t a[4], uint32_t b0, uint32_t b1) {
    asm volatile("mma.sync.aligned.m16n8k8.row.col.f32.tf32.tf32.f32 "
        "{%0,%1,%2,%3}, {%4,%5,%6,%7}, {%8,%9}, {%0,%1,%2,%3};\n"
        : "+f"(c[0]), "+f"(c[1]), "+f"(c[2]), "+f"(c[3])
        : "r"(a[0]), "r"(a[1]), "r"(a[2]), "r"(a[3]), "r"(b0), "r"(b1));
}

// ---------------------------------------------------------------------------
// TF32 wmma GEMM with cp.async double buffering.
// C[4096,1024] = A @ W + bias.  DST 0/1/2 -> head-major g_qh/g_kh/g_vh,
// DST 3 -> row-major `out` with A = g_attn.
// ---------------------------------------------------------------------------
#define G_ALD 36
#define G_BLD 132
#define G_ASZ (128 * G_ALD)
#define G_BSZ (32 * G_BLD)
#define GEMM_SMEM ((2 * G_ASZ + 2 * G_BSZ) * (int)sizeof(float))  // 70656

template<int DST>
__global__ __launch_bounds__(256)
void gemm_tf32_kernel(const float* __restrict__ A,
                      const float* __restrict__ W,
                      const float* __restrict__ bias,
                      float* __restrict__ out)
{
    extern __shared__ float gsm[];
    float* Asm = gsm;                   // [2][128][36]
    float* Bsm = gsm + 2 * G_ASZ;       // [2][32][132]
    __shared__ float stage[8][256];

    const float* Ap = (DST == 3) ? g_attn : A;

    const int tid    = threadIdx.x;
    const int wid    = tid >> 5;
    const int lane   = tid & 31;
    const int warp_m = wid >> 1;
    const int warp_n = wid & 1;
    const int m0 = blockIdx.y * 128;
    const int n0 = blockIdx.x * 128;

    wmma::fragment<wmma::accumulator, 16, 16, 8, float> acc[2][4];
#pragma unroll
    for (int i = 0; i < 2; i++)
#pragma unroll
        for (int j = 0; j < 4; j++)
            wmma::fill_fragment(acc[i][j], 0.0f);

#define GEMM_PREFETCH(IT, BUF)                                                      \
    {                                                                               \
        int k0 = (IT) * 32;                                                         \
        _Pragma("unroll")                                                           \
        for (int i = 0; i < 4; i++) {                                               \
            int idx = tid + i * 256;                                                \
            int r = idx >> 3, c4 = idx & 7;                                         \
            cp_async16(&Asm[(BUF) * G_ASZ + r * G_ALD + c4 * 4],                    \
                       Ap + (size_t)(m0 + r) * DMODEL + k0 + c4 * 4);               \
        }                                                                           \
        _Pragma("unroll")                                                           \
        for (int i = 0; i < 4; i++) {                                               \
            int idx = tid + i * 256;                                                \
            int r = idx >> 5, c4 = idx & 31;                                        \
            cp_async16(&Bsm[(BUF) * G_BSZ + r * G_BLD + c4 * 4],                    \
                       W + (size_t)(k0 + r) * DMODEL + n0 + c4 * 4);                \
        }                                                                           \
        cp_commit();                                                                \
    }

    GEMM_PREFETCH(0, 0);
    GEMM_PREFETCH(1, 1);

    for (int it = 0; it < 32; it++) {
        if (it + 1 < 32) cp_wait<1>(); else cp_wait<0>();
        __syncthreads();

        const int buf = it & 1;
        const float* Asb = Asm + buf * G_ASZ;
        const float* Bsb = Bsm + buf * G_BSZ;

#pragma unroll
        for (int kf = 0; kf < 4; kf++) {
            wmma::fragment<wmma::matrix_a, 16, 16, 8, wmma::precision::tf32, wmma::row_major> a[2];
            wmma::fragment<wmma::matrix_b, 16, 16, 8, wmma::precision::tf32, wmma::row_major> b[4];
#pragma unroll
            for (int i = 0; i < 2; i++) {
                wmma::load_matrix_sync(a[i], Asb + (warp_m * 32 + i * 16) * G_ALD + kf * 8, G_ALD);
#pragma unroll
                for (int t = 0; t < a[i].num_elements; t++)
                    a[i].x[t] = wmma::__float_to_tf32(a[i].x[t]);
            }
#pragma unroll
            for (int j = 0; j < 4; j++) {
                wmma::load_matrix_sync(b[j], Bsb + (kf * 8) * G_BLD + warp_n * 64 + j * 16, G_BLD);
#pragma unroll
                for (int t = 0; t < b[j].num_elements; t++)
                    b[j].x[t] = wmma::__float_to_tf32(b[j].x[t]);
            }
#pragma unroll
            for (int i = 0; i < 2; i++)
#pragma unroll
                for (int j = 0; j < 4; j++)
                    wmma::mma_sync(acc[i][j], a[i], b[j], acc[i][j]);
        }
        __syncthreads();
        if (it + 2 < 32) GEMM_PREFETCH(it + 2, buf);
    }
#undef GEMM_PREFETCH

    // Epilogue
#pragma unroll
    for (int i = 0; i < 2; i++) {
#pragma unroll
        for (int j = 0; j < 4; j++) {
            wmma::store_matrix_sync(&stage[wid][0], acc[i][j], 16, wmma::mem_row_major);
            __syncwarp();
            int grow0 = m0 + warp_m * 32 + i * 16;
            int gcol0 = n0 + warp_n * 64 + j * 16;
#pragma unroll
            for (int t = lane; t < 256; t += 32) {
                int r = t >> 4, c = t & 15;
                int grow = grow0 + r;
                int gcol = gcol0 + c;
                float v = stage[wid][t] + bias[gcol];
                if (DST <= 2) {
                    int b_ = grow >> 11;
                    int qr = grow & 2047;
                    int h_ = gcol >> 6;
                    int d_ = gcol & 63;
                    size_t addr = (((size_t)(b_ * NHEADS + h_) * SQ) + qr) * DHEAD + d_;
                    if (DST == 0) g_qh[addr] = v;
                    else if (DST == 1) g_kh[addr] = v;
                    else g_vh[addr] = v;
                } else {
                    out[(size_t)grow * DMODEL + gcol] = v;
                }
            }
            __syncwarp();
        }
    }
}

// ---------------------------------------------------------------------------
// Flash attention v2: register-resident S and O via PTX mma.m16n8k8.tf32.
// One CTA = 128 query rows (8 warps x 16 rows), 64-key tiles, cp.async
// double-buffered K/V. Q fragments live in registers for the whole kernel.
//
// m16n8k8 fragment layouts (g = lane>>2, q = lane&3):
//   A(16x8): a0=(g,q) a1=(g+8,q) a2=(g,q+4) a3=(g+8,q+4)
//   B(8x8) col-major: b0=(k=q,n=g) b1=(k=q+4,n=g)
//   C(16x8): c0=(g,2q) c1=(g,2q+1) c2=(g+8,2q) c3=(g+8,2q+1)
// ---------------------------------------------------------------------------
#define KLD 68   // conflict-free: bank = (4g+q) distinct over the warp
#define VLD 72   // conflict-free: bank = (8q+g) distinct over the warp
#define FL_KSZ (64 * KLD)
#define FL_VSZ (64 * VLD)
#define FLASH_SMEM ((2 * FL_KSZ + 2 * FL_VSZ) * (int)sizeof(float))  // 71680

__global__ __launch_bounds__(256)
void flash_attn_kernel()
{
    extern __shared__ float sm[];
    float* Ksm = sm;                  // [2][64][KLD]; also Q staging (128 x KLD)
    float* Vsm = sm + 2 * FL_KSZ;     // [2][64][VLD]

    const int q0  = blockIdx.x * 128;
    const int h   = blockIdx.y;
    const int b   = blockIdx.z;
    const int tid = threadIdx.x;
    const int wid = tid >> 5;
    const int lane = tid & 31;
    const int g = lane >> 2;
    const int q = lane & 3;

    const float* Qg = g_qh + (((size_t)(b * NHEADS + h) * SQ) + q0) * DHEAD;
    const float* Kg = g_kh + ((size_t)(b * NHEADS + h) * SK) * DHEAD;
    const float* Vg = g_vh + ((size_t)(b * NHEADS + h) * SK) * DHEAD;

    // ---- Stage Q tile (128x64) into Ksm area, build register fragments ----
#pragma unroll
    for (int i = 0; i < 8; i++) {
        int idx = tid + i * 256;
        int r = idx >> 4, c4 = idx & 15;
        cp_async16(&Ksm[r * KLD + c4 * 4], Qg + (size_t)r * DHEAD + c4 * 4);
    }
    cp_commit();
    cp_wait<0>();
    __syncthreads();

    uint32_t qa[8][4];
    {
        const float* Qw = Ksm + (wid * 16) * KLD;
#pragma unroll
        for (int kc = 0; kc < 8; kc++) {
            qa[kc][0] = f2tf32(0.125f * Qw[g * KLD + kc * 8 + q]);
            qa[kc][1] = f2tf32(0.125f * Qw[(g + 8) * KLD + kc * 8 + q]);
            qa[kc][2] = f2tf32(0.125f * Qw[g * KLD + kc * 8 + q + 4]);
            qa[kc][3] = f2tf32(0.125f * Qw[(g + 8) * KLD + kc * 8 + q + 4]);
        }
    }
    __syncthreads();   // everyone done reading Q before K overwrites

#define FL_PREFETCH(J, BUF)                                                         \
    {                                                                               \
        _Pragma("unroll")                                                           \
        for (int i = 0; i < 4; i++) {                                               \
            int idx = tid + i * 256;                                                \
            int r = idx >> 4, c4 = idx & 15;                                        \
            cp_async16(&Ksm[(BUF) * FL_KSZ + r * KLD + c4 * 4],                     \
                       Kg + (size_t)((J) * 64 + r) * DHEAD + c4 * 4);               \
            cp_async16(&Vsm[(BUF) * FL_VSZ + r * VLD + c4 * 4],                     \
                       Vg + (size_t)((J) * 64 + r) * DHEAD + c4 * 4);               \
        }                                                                           \
        cp_commit();                                                                \
    }

    FL_PREFETCH(0, 0);
    FL_PREFETCH(1, 1);

    float oacc[8][4];
#pragma unroll
    for (int nb = 0; nb < 8; nb++)
#pragma unroll
        for (int t = 0; t < 4; t++) oacc[nb][t] = 0.0f;

    float m0r = -CUDART_INF_F, m1r = -CUDART_INF_F;
    float l0r = 0.0f, l1r = 0.0f;

    const int NT = SK / 64;  // 32
    for (int j = 0; j < NT; j++) {
        if (j + 1 < NT) cp_wait<1>(); else cp_wait<0>();
        __syncthreads();

        const int buf = j & 1;
        const float* Kb = Ksm + buf * FL_KSZ;
        const float* Vb = Vsm + buf * FL_VSZ;

        // ---- S = (Q/sqrt(d)) K^T : register accumulators ----
        float sacc[8][4];
#pragma unroll
        for (int nb = 0; nb < 8; nb++) {
#pragma unroll
            for (int t = 0; t < 4; t++) sacc[nb][t] = 0.0f;
#pragma unroll
            for (int kc = 0; kc < 8; kc++) {
                uint32_t b0 = f2tf32(Kb[(nb * 8 + g) * KLD + kc * 8 + q]);
                uint32_t b1 = f2tf32(Kb[(nb * 8 + g) * KLD + kc * 8 + q + 4]);
                mma_tf32(sacc[nb], qa[kc], b0, b1);
            }
        }

        // ---- online softmax on registers (rows g and g+8) ----
        float mx0 = -CUDART_INF_F, mx1 = -CUDART_INF_F;
#pragma unroll
        for (int nb = 0; nb < 8; nb++) {
            mx0 = fmaxf(mx0, fmaxf(sacc[nb][0], sacc[nb][1]));
            mx1 = fmaxf(mx1, fmaxf(sacc[nb][2], sacc[nb][3]));
        }
        mx0 = fmaxf(mx0, __shfl_xor_sync(0xffffffffu, mx0, 1));
        mx0 = fmaxf(mx0, __shfl_xor_sync(0xffffffffu, mx0, 2));
        mx1 = fmaxf(mx1, __shfl_xor_sync(0xffffffffu, mx1, 1));
        mx1 = fmaxf(mx1, __shfl_xor_sync(0xffffffffu, mx1, 2));

        float mn0 = fmaxf(m0r, mx0), mn1 = fmaxf(m1r, mx1);
        float al0 = __expf(m0r - mn0), al1 = __expf(m1r - mn1);
        m0r = mn0; m1r = mn1;

        float s0 = 0.0f, s1 = 0.0f;
#pragma unroll
        for (int nb = 0; nb < 8; nb++) {
            sacc[nb][0] = __expf(sacc[nb][0] - mn0); s0 += sacc[nb][0];
            sacc[nb][1] = __expf(sacc[nb][1] - mn0); s0 += sacc[nb][1];
            sacc[nb][2] = __expf(sacc[nb][2] - mn1); s1 += sacc[nb][2];
            sacc[nb][3] = __expf(sacc[nb][3] - mn1); s1 += sacc[nb][3];
        }
        s0 += __shfl_xor_sync(0xffffffffu, s0, 1);
        s0 += __shfl_xor_sync(0xffffffffu, s0, 2);
        s1 += __shfl_xor_sync(0xffffffffu, s1, 1);
        s1 += __shfl_xor_sync(0xffffffffu, s1, 2);
        l0r = l0r * al0 + s0;
        l1r = l1r * al1 + s1;

#pragma unroll
        for (int nb = 0; nb < 8; nb++) {
            oacc[nb][0] *= al0; oacc[nb][1] *= al0;
            oacc[nb][2] *= al1; oacc[nb][3] *= al1;
        }

        // ---- O += P @ V : permute P accum layout -> A layout via shuffles ----
        const int src1 = (lane & ~3) | (q >> 1);
        const int src2 = src1 + 2;
        const bool odd = (q & 1);
#pragma unroll
        for (int kc = 0; kc < 8; kc++) {
            float e, o;
            uint32_t pa[4];
            e = __shfl_sync(0xffffffffu, sacc[kc][0], src1);
            o = __shfl_sync(0xffffffffu, sacc[kc][1], src1);
            pa[0] = f2tf32(odd ? o : e);
            e = __shfl_sync(0xffffffffu, sacc[kc][2], src1);
            o = __shfl_sync(0xffffffffu, sacc[kc][3], src1);
            pa[1] = f2tf32(odd ? o : e);
            e = __shfl_sync(0xffffffffu, sacc[kc][0], src2);
            o = __shfl_sync(0xffffffffu, sacc[kc][1], src2);
            pa[2] = f2tf32(odd ? o : e);
            e = __shfl_sync(0xffffffffu, sacc[kc][2], src2);
            o = __shfl_sync(0xffffffffu, sacc[kc][3], src2);
            pa[3] = f2tf32(odd ? o : e);
#pragma unroll
            for (int nb = 0; nb < 8; nb++) {
                uint32_t vb0 = f2tf32(Vb[(kc * 8 + q) * VLD + nb * 8 + g]);
                uint32_t vb1 = f2tf32(Vb[(kc * 8 + q + 4) * VLD + nb * 8 + g]);
                mma_tf32(oacc[nb], pa, vb0, vb1);
            }
        }

        __syncthreads();
        if (j + 2 < NT) FL_PREFETCH(j + 2, buf);
    }
#undef FL_PREFETCH

    // ---- normalize + write merged [b, q, h*64+d] directly from registers ----
    float inv0 = 1.0f / l0r, inv1 = 1.0f / l1r;
    int r0 = q0 + wid * 16 + g;
    float* og0 = g_attn + ((size_t)(b * SQ + r0) * DMODEL) + h * DHEAD;
    float* og1 = g_attn + ((size_t)(b * SQ + r0 + 8) * DMODEL) + h * DHEAD;
#pragma unroll
    for (int nb = 0; nb < 8; nb++) {
        float2 v0 = make_float2(oacc[nb][0] * inv0, oacc[nb][1] * inv0);
        float2 v1 = make_float2(oacc[nb][2] * inv1, oacc[nb][3] * inv1);
        *(float2*)(og0 + nb * 8 + 2 * q) = v0;
        *(float2*)(og1 + nb * 8 + 2 * q) = v1;
    }
}

// ---------------------------------------------------------------------------
// Launch
// ---------------------------------------------------------------------------
extern "C" void kernel_launch(void* const* d_in, const int* in_sizes, int n_in,
                              void* d_out, int out_size)
{
    const float* q  = (const float*)d_in[0];
    const float* k  = (const float*)d_in[1];
    const float* v  = (const float*)d_in[2];
    const float* Wq = (const float*)d_in[3];
    const float* bq = (const float*)d_in[4];
    const float* Wk = (const float*)d_in[5];
    const float* bk = (const float*)d_in[6];
    const float* Wv = (const float*)d_in[7];
    const float* bv = (const float*)d_in[8];
    const float* Wo = (const float*)d_in[9];
    const float* bo = (const float*)d_in[10];
    float* out = (float*)d_out;

    static bool attr_done = false;
    if (!attr_done) {
        cudaFuncSetAttribute(gemm_tf32_kernel<0>, cudaFuncAttributeMaxDynamicSharedMemorySize, GEMM_SMEM);
        cudaFuncSetAttribute(gemm_tf32_kernel<1>, cudaFuncAttributeMaxDynamicSharedMemorySize, GEMM_SMEM);
        cudaFuncSetAttribute(gemm_tf32_kernel<2>, cudaFuncAttributeMaxDynamicSharedMemorySize, GEMM_SMEM);
        cudaFuncSetAttribute(gemm_tf32_kernel<3>, cudaFuncAttributeMaxDynamicSharedMemorySize, GEMM_SMEM);
        cudaFuncSetAttribute(flash_attn_kernel, cudaFuncAttributeMaxDynamicSharedMemorySize, FLASH_SMEM);
        attr_done = true;
    }

    dim3 gblock(256);
    dim3 ggrid(DMODEL / 128, MROWS / 128);   // (8, 32)

    gemm_tf32_kernel<0><<<ggrid, gblock, GEMM_SMEM>>>(q, Wq, bq, nullptr);
    gemm_tf32_kernel<1><<<ggrid, gblock, GEMM_SMEM>>>(k, Wk, bk, nullptr);
    gemm_tf32_kernel<2><<<ggrid, gblock, GEMM_SMEM>>>(v, Wv, bv, nullptr);

    dim3 fgrid(SQ / 128, NHEADS, NBATCH);    // (16, 16, 2)
    flash_attn_kernel<<<fgrid, 256, FLASH_SMEM>>>();

    gemm_tf32_kernel<3><<<ggrid, gblock, GEMM_SMEM>>>(nullptr, Wo, bo, out);
}

// round 5
// speedup vs baseline: 2.0805x; 1.1652x over previous
#include <cuda_runtime.h>
#include <cuda_bf16.h>
#include <mma.h>
#include <math_constants.h>
#include <cstdint>

using namespace nvcuda;

#define DMODEL 1024
#define NHEADS 16
#define DHEAD  64
#define NBATCH 2
#define SQ     2048
#define SK     2048
#define MROWS  (NBATCH * SQ)   // 4096

// ---------------------------------------------------------------------------
// Scratch (device globals: no allocation allowed)
// ---------------------------------------------------------------------------
__device__ float g_qh[(size_t)NBATCH * NHEADS * SQ * DHEAD];   // [b,h,q,d]
__device__ float g_kh[(size_t)NBATCH * NHEADS * SK * DHEAD];
__device__ float g_vh[(size_t)NBATCH * NHEADS * SK * DHEAD];
__device__ float g_attn[(size_t)NBATCH * SQ * DMODEL];          // [b,q, h*64+d]

// ---------------------------------------------------------------------------
// helpers
// ---------------------------------------------------------------------------
__device__ __forceinline__ void cp_async16(void* smem, const void* gmem) {
    uint32_t s = (uint32_t)__cvta_generic_to_shared(smem);
    asm volatile("cp.async.cg.shared.global [%0], [%1], 16;\n" :: "r"(s), "l"(gmem));
}
__device__ __forceinline__ void cp_commit() { asm volatile("cp.async.commit_group;\n"); }
template<int N> __device__ __forceinline__ void cp_wait() {
    asm volatile("cp.async.wait_group %0;\n" :: "n"(N));
}
__device__ __forceinline__ uint32_t f2tf32(float f) {
    uint32_t r; asm("cvt.rna.tf32.f32 %0, %1;" : "=r"(r) : "f"(f)); return r;
}
__device__ __forceinline__ void mma_tf32(float c[4], const uint32_t a[4], uint32_t b0, uint32_t b1) {
    asm volatile("mma.sync.aligned.m16n8k8.row.col.f32.tf32.tf32.f32 "
        "{%0,%1,%2,%3}, {%4,%5,%6,%7}, {%8,%9}, {%0,%1,%2,%3};\n"
        : "+f"(c[0]), "+f"(c[1]), "+f"(c[2]), "+f"(c[3])
        : "r"(a[0]), "r"(a[1]), "r"(a[2]), "r"(a[3]), "r"(b0), "r"(b1));
}

// ---------------------------------------------------------------------------
// TF32 GEMM v2: CTA 128x128, 4 warps, warp tile 64x64 (4x4 m16n16k8 frags),
// BK=32, cp.async double buffering.
// C[4096,1024] = A @ W + bias. DST 0/1/2 -> head-major g_qh/g_kh/g_vh,
// DST 3 -> row-major `out` with A = g_attn.
// ---------------------------------------------------------------------------
#define G_ALD 36
#define G_BLD 132
#define G_ASZ (128 * G_ALD)
#define G_BSZ (32 * G_BLD)
#define GEMM_SMEM ((2 * G_ASZ + 2 * G_BSZ) * (int)sizeof(float))  // 70656

template<int DST>
__global__ __launch_bounds__(128)
void gemm_tf32_kernel(const float* __restrict__ A,
                      const float* __restrict__ W,
                      const float* __restrict__ bias,
                      float* __restrict__ out)
{
    extern __shared__ float gsm[];
    float* Asm = gsm;                   // [2][128][36]
    float* Bsm = gsm + 2 * G_ASZ;       // [2][32][132]
    __shared__ float stage[4][256];

    const float* Ap = (DST == 3) ? g_attn : A;

    const int tid    = threadIdx.x;
    const int wid    = tid >> 5;
    const int lane   = tid & 31;
    const int warp_m = wid >> 1;   // 0..1
    const int warp_n = wid & 1;    // 0..1
    const int m0 = blockIdx.y * 128;
    const int n0 = blockIdx.x * 128;

    wmma::fragment<wmma::accumulator, 16, 16, 8, float> acc[4][4];
#pragma unroll
    for (int i = 0; i < 4; i++)
#pragma unroll
        for (int j = 0; j < 4; j++)
            wmma::fill_fragment(acc[i][j], 0.0f);

#define GEMM_PREFETCH(IT, BUF)                                                      \
    {                                                                               \
        int k0 = (IT) * 32;                                                         \
        _Pragma("unroll")                                                           \
        for (int i = 0; i < 8; i++) {                                               \
            int idx = tid + i * 128;                                                \
            int r = idx >> 3, c4 = idx & 7;                                         \
            cp_async16(&Asm[(BUF) * G_ASZ + r * G_ALD + c4 * 4],                    \
                       Ap + (size_t)(m0 + r) * DMODEL + k0 + c4 * 4);               \
        }                                                                           \
        _Pragma("unroll")                                                           \
        for (int i = 0; i < 8; i++) {                                               \
            int idx = tid + i * 128;                                                \
            int r = idx >> 5, c4 = idx & 31;                                        \
            cp_async16(&Bsm[(BUF) * G_BSZ + r * G_BLD + c4 * 4],                    \
                       W + (size_t)(k0 + r) * DMODEL + n0 + c4 * 4);                \
        }                                                                           \
        cp_commit();                                                                \
    }

    GEMM_PREFETCH(0, 0);
    GEMM_PREFETCH(1, 1);

    for (int it = 0; it < 32; it++) {
        if (it + 1 < 32) cp_wait<1>(); else cp_wait<0>();
        __syncthreads();

        const int buf = it & 1;
        const float* Asb = Asm + buf * G_ASZ;
        const float* Bsb = Bsm + buf * G_BSZ;

#pragma unroll
        for (int kf = 0; kf < 4; kf++) {
            wmma::fragment<wmma::matrix_a, 16, 16, 8, wmma::precision::tf32, wmma::row_major> a[4];
            wmma::fragment<wmma::matrix_b, 16, 16, 8, wmma::precision::tf32, wmma::row_major> b[4];
#pragma unroll
            for (int i = 0; i < 4; i++) {
                wmma::load_matrix_sync(a[i], Asb + (warp_m * 64 + i * 16) * G_ALD + kf * 8, G_ALD);
#pragma unroll
                for (int t = 0; t < a[i].num_elements; t++)
                    a[i].x[t] = wmma::__float_to_tf32(a[i].x[t]);
            }
#pragma unroll
            for (int j = 0; j < 4; j++) {
                wmma::load_matrix_sync(b[j], Bsb + (kf * 8) * G_BLD + warp_n * 64 + j * 16, G_BLD);
#pragma unroll
                for (int t = 0; t < b[j].num_elements; t++)
                    b[j].x[t] = wmma::__float_to_tf32(b[j].x[t]);
            }
#pragma unroll
            for (int i = 0; i < 4; i++)
#pragma unroll
                for (int j = 0; j < 4; j++)
                    wmma::mma_sync(acc[i][j], a[i], b[j], acc[i][j]);
        }
        __syncthreads();
        if (it + 2 < 32) GEMM_PREFETCH(it + 2, buf);
    }
#undef GEMM_PREFETCH

    // Epilogue
#pragma unroll
    for (int i = 0; i < 4; i++) {
#pragma unroll
        for (int j = 0; j < 4; j++) {
            wmma::store_matrix_sync(&stage[wid][0], acc[i][j], 16, wmma::mem_row_major);
            __syncwarp();
            int grow0 = m0 + warp_m * 64 + i * 16;
            int gcol0 = n0 + warp_n * 64 + j * 16;
#pragma unroll
            for (int t = lane; t < 256; t += 32) {
                int r = t >> 4, c = t & 15;
                int grow = grow0 + r;
                int gcol = gcol0 + c;
                float v = stage[wid][t] + bias[gcol];
                if (DST <= 2) {
                    int b_ = grow >> 11;
                    int qr = grow & 2047;
                    int h_ = gcol >> 6;
                    int d_ = gcol & 63;
                    size_t addr = (((size_t)(b_ * NHEADS + h_) * SQ) + qr) * DHEAD + d_;
                    if (DST == 0) g_qh[addr] = v;
                    else if (DST == 1) g_kh[addr] = v;
                    else g_vh[addr] = v;
                } else {
                    out[(size_t)grow * DMODEL + gcol] = v;
                }
            }
            __syncwarp();
        }
    }
}

// ---------------------------------------------------------------------------
// Flash attention v3: register-resident S/O, and K/V tiles are converted to
// tf32 IN SMEM once per tile (cooperative pass) so the mainloop issues plain
// LDS with zero per-fragment converts.
//
// m16n8k8 fragment layouts (g = lane>>2, q = lane&3):
//   A(16x8): a0=(g,q) a1=(g+8,q) a2=(g,q+4) a3=(g+8,q+4)
//   B(8x8) col-major: b0=(k=q,n=g) b1=(k=q+4,n=g)
//   C(16x8): c0=(g,2q) c1=(g,2q+1) c2=(g+8,2q) c3=(g+8,2q+1)
// ---------------------------------------------------------------------------
#define KLD 68
#define VLD 72
#define FL_KSZ (64 * KLD)
#define FL_VSZ (64 * VLD)
#define FLASH_SMEM ((2 * FL_KSZ + 2 * FL_VSZ) * (int)sizeof(float))  // 71680

__global__ __launch_bounds__(256)
void flash_attn_kernel()
{
    extern __shared__ float sm[];
    float* Ksm = sm;                  // [2][64][KLD]; also Q staging (128 x KLD)
    float* Vsm = sm + 2 * FL_KSZ;     // [2][64][VLD]

    const int q0  = blockIdx.x * 128;
    const int h   = blockIdx.y;
    const int b   = blockIdx.z;
    const int tid = threadIdx.x;
    const int wid = tid >> 5;
    const int lane = tid & 31;
    const int g = lane >> 2;
    const int q = lane & 3;

    const float* Qg = g_qh + (((size_t)(b * NHEADS + h) * SQ) + q0) * DHEAD;
    const float* Kg = g_kh + ((size_t)(b * NHEADS + h) * SK) * DHEAD;
    const float* Vg = g_vh + ((size_t)(b * NHEADS + h) * SK) * DHEAD;

    // ---- Stage Q tile (128x64) into Ksm area, build register fragments ----
#pragma unroll
    for (int i = 0; i < 8; i++) {
        int idx = tid + i * 256;
        int r = idx >> 4, c4 = idx & 15;
        cp_async16(&Ksm[r * KLD + c4 * 4], Qg + (size_t)r * DHEAD + c4 * 4);
    }
    cp_commit();
    cp_wait<0>();
    __syncthreads();

    uint32_t qa[8][4];
    {
        const float* Qw = Ksm + (wid * 16) * KLD;
#pragma unroll
        for (int kc = 0; kc < 8; kc++) {
            qa[kc][0] = f2tf32(0.125f * Qw[g * KLD + kc * 8 + q]);
            qa[kc][1] = f2tf32(0.125f * Qw[(g + 8) * KLD + kc * 8 + q]);
            qa[kc][2] = f2tf32(0.125f * Qw[g * KLD + kc * 8 + q + 4]);
            qa[kc][3] = f2tf32(0.125f * Qw[(g + 8) * KLD + kc * 8 + q + 4]);
        }
    }
    __syncthreads();   // everyone done reading Q before K overwrites

#define FL_PREFETCH(J, BUF)                                                         \
    {                                                                               \
        _Pragma("unroll")                                                           \
        for (int i = 0; i < 4; i++) {                                               \
            int idx = tid + i * 256;                                                \
            int r = idx >> 4, c4 = idx & 15;                                        \
            cp_async16(&Ksm[(BUF) * FL_KSZ + r * KLD + c4 * 4],                     \
                       Kg + (size_t)((J) * 64 + r) * DHEAD + c4 * 4);               \
            cp_async16(&Vsm[(BUF) * FL_VSZ + r * VLD + c4 * 4],                     \
                       Vg + (size_t)((J) * 64 + r) * DHEAD + c4 * 4);               \
        }                                                                           \
        cp_commit();                                                                \
    }

    FL_PREFETCH(0, 0);
    FL_PREFETCH(1, 1);

    float oacc[8][4];
#pragma unroll
    for (int nb = 0; nb < 8; nb++)
#pragma unroll
        for (int t = 0; t < 4; t++) oacc[nb][t] = 0.0f;

    float m0r = -CUDART_INF_F, m1r = -CUDART_INF_F;
    float l0r = 0.0f, l1r = 0.0f;

    const int NT = SK / 64;  // 32
    for (int j = 0; j < NT; j++) {
        if (j + 1 < NT) cp_wait<1>(); else cp_wait<0>();
        __syncthreads();

        const int buf = j & 1;

        // ---- cooperative in-place f32 -> tf32 conversion of K & V tiles ----
        {
            float4* kp = (float4*)(Ksm + buf * FL_KSZ);      // 64*KLD/4 = 1088
            float4* vp = (float4*)(Vsm + buf * FL_VSZ);      // 64*VLD/4 = 1152
#pragma unroll
            for (int i = 0; i < 5; i++) {
                int idx = tid + i * 256;
                if (idx < FL_KSZ / 4) {
                    float4 v = kp[idx];
                    uint4 u;
                    u.x = f2tf32(v.x); u.y = f2tf32(v.y);
                    u.z = f2tf32(v.z); u.w = f2tf32(v.w);
                    ((uint4*)kp)[idx] = u;
                }
                if (idx < FL_VSZ / 4) {
                    float4 v = vp[idx];
                    uint4 u;
                    u.x = f2tf32(v.x); u.y = f2tf32(v.y);
                    u.z = f2tf32(v.z); u.w = f2tf32(v.w);
                    ((uint4*)vp)[idx] = u;
                }
            }
        }
        __syncthreads();

        const uint32_t* Kb = (const uint32_t*)(Ksm + buf * FL_KSZ);
        const uint32_t* Vb = (const uint32_t*)(Vsm + buf * FL_VSZ);

        // ---- S = (Q/sqrt(d)) K^T : register accumulators ----
        float sacc[8][4];
#pragma unroll
        for (int nb = 0; nb < 8; nb++) {
#pragma unroll
            for (int t = 0; t < 4; t++) sacc[nb][t] = 0.0f;
#pragma unroll
            for (int kc = 0; kc < 8; kc++) {
                uint32_t b0 = Kb[(nb * 8 + g) * KLD + kc * 8 + q];
                uint32_t b1 = Kb[(nb * 8 + g) * KLD + kc * 8 + q + 4];
                mma_tf32(sacc[nb], qa[kc], b0, b1);
            }
        }

        // ---- online softmax on registers (rows g and g+8) ----
        float mx0 = -CUDART_INF_F, mx1 = -CUDART_INF_F;
#pragma unroll
        for (int nb = 0; nb < 8; nb++) {
            mx0 = fmaxf(mx0, fmaxf(sacc[nb][0], sacc[nb][1]));
            mx1 = fmaxf(mx1, fmaxf(sacc[nb][2], sacc[nb][3]));
        }
        mx0 = fmaxf(mx0, __shfl_xor_sync(0xffffffffu, mx0, 1));
        mx0 = fmaxf(mx0, __shfl_xor_sync(0xffffffffu, mx0, 2));
        mx1 = fmaxf(mx1, __shfl_xor_sync(0xffffffffu, mx1, 1));
        mx1 = fmaxf(mx1, __shfl_xor_sync(0xffffffffu, mx1, 2));

        float mn0 = fmaxf(m0r, mx0), mn1 = fmaxf(m1r, mx1);
        float al0 = __expf(m0r - mn0), al1 = __expf(m1r - mn1);
        m0r = mn0; m1r = mn1;

        float s0 = 0.0f, s1 = 0.0f;
#pragma unroll
        for (int nb = 0; nb < 8; nb++) {
            sacc[nb][0] = __expf(sacc[nb][0] - mn0); s0 += sacc[nb][0];
            sacc[nb][1] = __expf(sacc[nb][1] - mn0); s0 += sacc[nb][1];
            sacc[nb][2] = __expf(sacc[nb][2] - mn1); s1 += sacc[nb][2];
            sacc[nb][3] = __expf(sacc[nb][3] - mn1); s1 += sacc[nb][3];
        }
        s0 += __shfl_xor_sync(0xffffffffu, s0, 1);
        s0 += __shfl_xor_sync(0xffffffffu, s0, 2);
        s1 += __shfl_xor_sync(0xffffffffu, s1, 1);
        s1 += __shfl_xor_sync(0xffffffffu, s1, 2);
        l0r = l0r * al0 + s0;
        l1r = l1r * al1 + s1;

#pragma unroll
        for (int nb = 0; nb < 8; nb++) {
            oacc[nb][0] *= al0; oacc[nb][1] *= al0;
            oacc[nb][2] *= al1; oacc[nb][3] *= al1;
        }

        // ---- O += P @ V : permute P accum layout -> A layout via shuffles ----
        const int src1 = (lane & ~3) | (q >> 1);
        const int src2 = src1 + 2;
        const bool odd = (q & 1);
#pragma unroll
        for (int kc = 0; kc < 8; kc++) {
            float e, o;
            uint32_t pa[4];
            e = __shfl_sync(0xffffffffu, sacc[kc][0], src1);
            o = __shfl_sync(0xffffffffu, sacc[kc][1], src1);
            pa[0] = f2tf32(odd ? o : e);
            e = __shfl_sync(0xffffffffu, sacc[kc][2], src1);
            o = __shfl_sync(0xffffffffu, sacc[kc][3], src1);
            pa[1] = f2tf32(odd ? o : e);
            e = __shfl_sync(0xffffffffu, sacc[kc][0], src2);
            o = __shfl_sync(0xffffffffu, sacc[kc][1], src2);
            pa[2] = f2tf32(odd ? o : e);
            e = __shfl_sync(0xffffffffu, sacc[kc][2], src2);
            o = __shfl_sync(0xffffffffu, sacc[kc][3], src2);
            pa[3] = f2tf32(odd ? o : e);
#pragma unroll
            for (int nb = 0; nb < 8; nb++) {
                uint32_t vb0 = Vb[(kc * 8 + q) * VLD + nb * 8 + g];
                uint32_t vb1 = Vb[(kc * 8 + q + 4) * VLD + nb * 8 + g];
                mma_tf32(oacc[nb], pa, vb0, vb1);
            }
        }

        __syncthreads();
        if (j + 2 < NT) FL_PREFETCH(j + 2, buf);
    }
#undef FL_PREFETCH

    // ---- normalize + write merged [b, q, h*64+d] directly from registers ----
    float inv0 = 1.0f / l0r, inv1 = 1.0f / l1r;
    int r0 = q0 + wid * 16 + g;
    float* og0 = g_attn + ((size_t)(b * SQ + r0) * DMODEL) + h * DHEAD;
    float* og1 = g_attn + ((size_t)(b * SQ + r0 + 8) * DMODEL) + h * DHEAD;
#pragma unroll
    for (int nb = 0; nb < 8; nb++) {
        float2 v0 = make_float2(oacc[nb][0] * inv0, oacc[nb][1] * inv0);
        float2 v1 = make_float2(oacc[nb][2] * inv1, oacc[nb][3] * inv1);
        *(float2*)(og0 + nb * 8 + 2 * q) = v0;
        *(float2*)(og1 + nb * 8 + 2 * q) = v1;
    }
}

// ---------------------------------------------------------------------------
// Launch
// ---------------------------------------------------------------------------
extern "C" void kernel_launch(void* const* d_in, const int* in_sizes, int n_in,
                              void* d_out, int out_size)
{
    const float* q  = (const float*)d_in[0];
    const float* k  = (const float*)d_in[1];
    const float* v  = (const float*)d_in[2];
    const float* Wq = (const float*)d_in[3];
    const float* bq = (const float*)d_in[4];
    const float* Wk = (const float*)d_in[5];
    const float* bk = (const float*)d_in[6];
    const float* Wv = (const float*)d_in[7];
    const float* bv = (const float*)d_in[8];
    const float* Wo = (const float*)d_in[9];
    const float* bo = (const float*)d_in[10];
    float* out = (float*)d_out;

    static bool attr_done = false;
    if (!attr_done) {
        cudaFuncSetAttribute(gemm_tf32_kernel<0>, cudaFuncAttributeMaxDynamicSharedMemorySize, GEMM_SMEM);
        cudaFuncSetAttribute(gemm_tf32_kernel<1>, cudaFuncAttributeMaxDynamicSharedMemorySize, GEMM_SMEM);
        cudaFuncSetAttribute(gemm_tf32_kernel<2>, cudaFuncAttributeMaxDynamicSharedMemorySize, GEMM_SMEM);
        cudaFuncSetAttribute(gemm_tf32_kernel<3>, cudaFuncAttributeMaxDynamicSharedMemorySize, GEMM_SMEM);
        cudaFuncSetAttribute(flash_attn_kernel, cudaFuncAttributeMaxDynamicSharedMemorySize, FLASH_SMEM);
        attr_done = true;
    }

    dim3 gblock(128);
    dim3 ggrid(DMODEL / 128, MROWS / 128);   // (8, 32)

    gemm_tf32_kernel<0><<<ggrid, gblock, GEMM_SMEM>>>(q, Wq, bq, nullptr);
    gemm_tf32_kernel<1><<<ggrid, gblock, GEMM_SMEM>>>(k, Wk, bk, nullptr);
    gemm_tf32_kernel<2><<<ggrid, gblock, GEMM_SMEM>>>(v, Wv, bv, nullptr);

    dim3 fgrid(SQ / 128, NHEADS, NBATCH);    // (16, 16, 2)
    flash_attn_kernel<<<fgrid, 256, FLASH_SMEM>>>();

    gemm_tf32_kernel<3><<<ggrid, gblock, GEMM_SMEM>>>(nullptr, Wo, bo, out);
}

// round 6
// speedup vs baseline: 2.1178x; 1.0179x over previous
#include <cuda_runtime.h>
#include <cuda_bf16.h>
#include <mma.h>
#include <math_constants.h>
#include <cstdint>

using namespace nvcuda;

#define DMODEL 1024
#define NHEADS 16
#define DHEAD  64
#define NBATCH 2
#define SQ     2048
#define SK     2048
#define MROWS  (NBATCH * SQ)   // 4096

// ---------------------------------------------------------------------------
// Scratch (device globals: no allocation allowed)
// ---------------------------------------------------------------------------
__device__ float g_qh[(size_t)NBATCH * NHEADS * SQ * DHEAD];   // [b,h,q,d] tf32 bits
__device__ float g_kh[(size_t)NBATCH * NHEADS * SK * DHEAD];   // tf32 bits
__device__ float g_vh[(size_t)NBATCH * NHEADS * SK * DHEAD];   // tf32 bits
__device__ float g_attn[(size_t)NBATCH * SQ * DMODEL];          // [b,q,h*64+d] tf32 bits
__device__ float g_act[(size_t)3 * MROWS * DMODEL];             // tf32(q,k,v)
__device__ float g_w[(size_t)3 * DMODEL * DMODEL];              // tf32(Wq,Wk,Wv)
__device__ float g_wo[(size_t)DMODEL * DMODEL];                 // tf32(Wo)

// ---------------------------------------------------------------------------
// helpers
// ---------------------------------------------------------------------------
__device__ __forceinline__ void cp_async16(void* smem, const void* gmem) {
    uint32_t s = (uint32_t)__cvta_generic_to_shared(smem);
    asm volatile("cp.async.cg.shared.global [%0], [%1], 16;\n" :: "r"(s), "l"(gmem));
}
__device__ __forceinline__ void cp_commit() { asm volatile("cp.async.commit_group;\n"); }
template<int N> __device__ __forceinline__ void cp_wait() {
    asm volatile("cp.async.wait_group %0;\n" :: "n"(N));
}
__device__ __forceinline__ uint32_t f2tf32(float f) {
    uint32_t r; asm("cvt.rna.tf32.f32 %0, %1;" : "=r"(r) : "f"(f)); return r;
}
__device__ __forceinline__ void mma_tf32(float c[4], const uint32_t a[4], uint32_t b0, uint32_t b1) {
    asm volatile("mma.sync.aligned.m16n8k8.row.col.f32.tf32.tf32.f32 "
        "{%0,%1,%2,%3}, {%4,%5,%6,%7}, {%8,%9}, {%0,%1,%2,%3};\n"
        : "+f"(c[0]), "+f"(c[1]), "+f"(c[2]), "+f"(c[3])
        : "r"(a[0]), "r"(a[1]), "r"(a[2]), "r"(a[3]), "r"(b0), "r"(b1));
}

// ---------------------------------------------------------------------------
// Preconvert: round inputs + weights to tf32 bits once.
// grid (4096, 7): y=0..2 -> q,k,v (1048576 float4 each); y=3..6 -> Wq,Wk,Wv,Wo
// ---------------------------------------------------------------------------
__global__ __launch_bounds__(256)
void preconvert_kernel(const float4* __restrict__ q, const float4* __restrict__ k,
                       const float4* __restrict__ v, const float4* __restrict__ wq,
                       const float4* __restrict__ wk, const float4* __restrict__ wv,
                       const float4* __restrict__ wo)
{
    const int y = blockIdx.y;
    const float4* src;
    float4* dst;
    int n4;
    if (y < 3) {
        src = (y == 0) ? q : (y == 1) ? k : v;
        dst = (float4*)g_act + (size_t)y * (MROWS * DMODEL / 4);
        n4 = MROWS * DMODEL / 4;            // 1048576
    } else {
        src = (y == 3) ? wq : (y == 4) ? wk : (y == 5) ? wv : wo;
        dst = (y < 6) ? (float4*)g_w + (size_t)(y - 3) * (DMODEL * DMODEL / 4)
                      : (float4*)g_wo;
        n4 = DMODEL * DMODEL / 4;           // 262144
    }
    int idx = blockIdx.x * 256 + threadIdx.x;
    if (idx < n4) {
        float4 s = src[idx];
        uint4 u;
        u.x = f2tf32(s.x); u.y = f2tf32(s.y);
        u.z = f2tf32(s.z); u.w = f2tf32(s.w);
        ((uint4*)dst)[idx] = u;
    }
}

// ---------------------------------------------------------------------------
// TF32 GEMM v3: CTA 128x128, 4 warps, warp tile 64x64. Operands are already
// tf32 bits -> NO conversions in the inner loop.
// MODE 0: batched projections, grid.z in {0,1,2} selects (g_act, g_w, bias_z)
//         -> head-major g_qh/g_kh/g_vh, epilogue rounds to tf32 bits.
// MODE 1: out = g_attn @ g_wo + bo, plain fp32 row-major.
// ---------------------------------------------------------------------------
#define G_ALD 36
#define G_BLD 132
#define G_ASZ (128 * G_ALD)
#define G_BSZ (32 * G_BLD)
#define GEMM_SMEM ((2 * G_ASZ + 2 * G_BSZ) * (int)sizeof(float))  // 70656

template<int MODE>
__global__ __launch_bounds__(128)
void gemm_tf32_kernel(const float* __restrict__ bias0,
                      const float* __restrict__ bias1,
                      const float* __restrict__ bias2,
                      float* __restrict__ out)
{
    extern __shared__ float gsm[];
    float* Asm = gsm;                   // [2][128][36]
    float* Bsm = gsm + 2 * G_ASZ;       // [2][32][132]
    __shared__ float stage[4][256];

    const int z = blockIdx.z;
    const float* Ap   = (MODE == 1) ? g_attn : g_act + (size_t)z * (MROWS * DMODEL);
    const float* W    = (MODE == 1) ? g_wo   : g_w   + (size_t)z * (DMODEL * DMODEL);
    const float* bias = (MODE == 1) ? bias0  : (z == 0) ? bias0 : (z == 1) ? bias1 : bias2;

    const int tid    = threadIdx.x;
    const int wid    = tid >> 5;
    const int lane   = tid & 31;
    const int warp_m = wid >> 1;
    const int warp_n = wid & 1;
    const int m0 = blockIdx.y * 128;
    const int n0 = blockIdx.x * 128;

    wmma::fragment<wmma::accumulator, 16, 16, 8, float> acc[4][4];
#pragma unroll
    for (int i = 0; i < 4; i++)
#pragma unroll
        for (int j = 0; j < 4; j++)
            wmma::fill_fragment(acc[i][j], 0.0f);

#define GEMM_PREFETCH(IT, BUF)                                                      \
    {                                                                               \
        int k0 = (IT) * 32;                                                         \
        _Pragma("unroll")                                                           \
        for (int i = 0; i < 8; i++) {                                               \
            int idx = tid + i * 128;                                                \
            int r = idx >> 3, c4 = idx & 7;                                         \
            cp_async16(&Asm[(BUF) * G_ASZ + r * G_ALD + c4 * 4],                    \
                       Ap + (size_t)(m0 + r) * DMODEL + k0 + c4 * 4);               \
        }                                                                           \
        _Pragma("unroll")                                                           \
        for (int i = 0; i < 8; i++) {                                               \
            int idx = tid + i * 128;                                                \
            int r = idx >> 5, c4 = idx & 31;                                        \
            cp_async16(&Bsm[(BUF) * G_BSZ + r * G_BLD + c4 * 4],                    \
                       W + (size_t)(k0 + r) * DMODEL + n0 + c4 * 4);                \
        }                                                                           \
        cp_commit();                                                                \
    }

    GEMM_PREFETCH(0, 0);
    GEMM_PREFETCH(1, 1);

    for (int it = 0; it < 32; it++) {
        if (it + 1 < 32) cp_wait<1>(); else cp_wait<0>();
        __syncthreads();

        const int buf = it & 1;
        const float* Asb = Asm + buf * G_ASZ;
        const float* Bsb = Bsm + buf * G_BSZ;

#pragma unroll
        for (int kf = 0; kf < 4; kf++) {
            wmma::fragment<wmma::matrix_a, 16, 16, 8, wmma::precision::tf32, wmma::row_major> a[4];
            wmma::fragment<wmma::matrix_b, 16, 16, 8, wmma::precision::tf32, wmma::row_major> b[4];
#pragma unroll
            for (int i = 0; i < 4; i++)
                wmma::load_matrix_sync(a[i], Asb + (warp_m * 64 + i * 16) * G_ALD + kf * 8, G_ALD);
#pragma unroll
            for (int j = 0; j < 4; j++)
                wmma::load_matrix_sync(b[j], Bsb + (kf * 8) * G_BLD + warp_n * 64 + j * 16, G_BLD);
#pragma unroll
            for (int i = 0; i < 4; i++)
#pragma unroll
                for (int j = 0; j < 4; j++)
                    wmma::mma_sync(acc[i][j], a[i], b[j], acc[i][j]);
        }
        __syncthreads();
        if (it + 2 < 32) GEMM_PREFETCH(it + 2, buf);
    }
#undef GEMM_PREFETCH

    // Epilogue
#pragma unroll
    for (int i = 0; i < 4; i++) {
#pragma unroll
        for (int j = 0; j < 4; j++) {
            wmma::store_matrix_sync(&stage[wid][0], acc[i][j], 16, wmma::mem_row_major);
            __syncwarp();
            int grow0 = m0 + warp_m * 64 + i * 16;
            int gcol0 = n0 + warp_n * 64 + j * 16;
#pragma unroll
            for (int t = lane; t < 256; t += 32) {
                int r = t >> 4, c = t & 15;
                int grow = grow0 + r;
                int gcol = gcol0 + c;
                float v = stage[wid][t] + bias[gcol];
                if (MODE == 0) {
                    int b_ = grow >> 11;
                    int qr = grow & 2047;
                    int h_ = gcol >> 6;
                    int d_ = gcol & 63;
                    size_t addr = (((size_t)(b_ * NHEADS + h_) * SQ) + qr) * DHEAD + d_;
                    float vt = __uint_as_float(f2tf32(v));
                    if (z == 0) g_qh[addr] = vt;
                    else if (z == 1) g_kh[addr] = vt;
                    else g_vh[addr] = vt;
                } else {
                    out[(size_t)grow * DMODEL + gcol] = v;
                }
            }
            __syncwarp();
        }
    }
}

// ---------------------------------------------------------------------------
// Flash attention v4: K/V/Q arrive as tf32 bits -> no conversion pass, no
// per-fragment cvts. Register-resident S/O, cp.async double-buffered K/V.
//
// m16n8k8 fragment layouts (g = lane>>2, q = lane&3):
//   A(16x8): a0=(g,q) a1=(g+8,q) a2=(g,q+4) a3=(g+8,q+4)
//   B(8x8) col-major: b0=(k=q,n=g) b1=(k=q+4,n=g)
//   C(16x8): c0=(g,2q) c1=(g,2q+1) c2=(g+8,2q) c3=(g+8,2q+1)
// ---------------------------------------------------------------------------
#define KLD 68
#define VLD 72
#define FL_KSZ (64 * KLD)
#define FL_VSZ (64 * VLD)
#define FLASH_SMEM ((2 * FL_KSZ + 2 * FL_VSZ) * (int)sizeof(float))  // 71680

__global__ __launch_bounds__(256)
void flash_attn_kernel()
{
    extern __shared__ float sm[];
    float* Ksm = sm;                  // [2][64][KLD]; also Q staging (128 x KLD)
    float* Vsm = sm + 2 * FL_KSZ;     // [2][64][VLD]

    const int q0  = blockIdx.x * 128;
    const int h   = blockIdx.y;
    const int b   = blockIdx.z;
    const int tid = threadIdx.x;
    const int wid = tid >> 5;
    const int lane = tid & 31;
    const int g = lane >> 2;
    const int q = lane & 3;

    const float* Qg = g_qh + (((size_t)(b * NHEADS + h) * SQ) + q0) * DHEAD;
    const float* Kg = g_kh + ((size_t)(b * NHEADS + h) * SK) * DHEAD;
    const float* Vg = g_vh + ((size_t)(b * NHEADS + h) * SK) * DHEAD;

    // ---- Stage Q tile (128x64) into Ksm area, build register fragments ----
#pragma unroll
    for (int i = 0; i < 8; i++) {
        int idx = tid + i * 256;
        int r = idx >> 4, c4 = idx & 15;
        cp_async16(&Ksm[r * KLD + c4 * 4], Qg + (size_t)r * DHEAD + c4 * 4);
    }
    cp_commit();
    cp_wait<0>();
    __syncthreads();

    // Q is tf32 bits; * 0.125 (2^-3) is exact and stays tf32 -> no cvt needed.
    uint32_t qa[8][4];
    {
        const float* Qw = Ksm + (wid * 16) * KLD;
#pragma unroll
        for (int kc = 0; kc < 8; kc++) {
            qa[kc][0] = __float_as_uint(0.125f * Qw[g * KLD + kc * 8 + q]);
            qa[kc][1] = __float_as_uint(0.125f * Qw[(g + 8) * KLD + kc * 8 + q]);
            qa[kc][2] = __float_as_uint(0.125f * Qw[g * KLD + kc * 8 + q + 4]);
            qa[kc][3] = __float_as_uint(0.125f * Qw[(g + 8) * KLD + kc * 8 + q + 4]);
        }
    }
    __syncthreads();   // everyone done reading Q before K overwrites

#define FL_PREFETCH(J, BUF)                                                         \
    {                                                                               \
        _Pragma("unroll")                                                           \
        for (int i = 0; i < 4; i++) {                                               \
            int idx = tid + i * 256;                                                \
            int r = idx >> 4, c4 = idx & 15;                                        \
            cp_async16(&Ksm[(BUF) * FL_KSZ + r * KLD + c4 * 4],                     \
                       Kg + (size_t)((J) * 64 + r) * DHEAD + c4 * 4);               \
            cp_async16(&Vsm[(BUF) * FL_VSZ + r * VLD + c4 * 4],                     \
                       Vg + (size_t)((J) * 64 + r) * DHEAD + c4 * 4);               \
        }                                                                           \
        cp_commit();                                                                \
    }

    FL_PREFETCH(0, 0);
    FL_PREFETCH(1, 1);

    float oacc[8][4];
#pragma unroll
    for (int nb = 0; nb < 8; nb++)
#pragma unroll
        for (int t = 0; t < 4; t++) oacc[nb][t] = 0.0f;

    float m0r = -CUDART_INF_F, m1r = -CUDART_INF_F;
    float l0r = 0.0f, l1r = 0.0f;

    const int NT = SK / 64;  // 32
    for (int j = 0; j < NT; j++) {
        if (j + 1 < NT) cp_wait<1>(); else cp_wait<0>();
        __syncthreads();

        const int buf = j & 1;
        const uint32_t* Kb = (const uint32_t*)(Ksm + buf * FL_KSZ);
        const uint32_t* Vb = (const uint32_t*)(Vsm + buf * FL_VSZ);

        // ---- S = (Q/sqrt(d)) K^T : register accumulators ----
        float sacc[8][4];
#pragma unroll
        for (int nb = 0; nb < 8; nb++) {
#pragma unroll
            for (int t = 0; t < 4; t++) sacc[nb][t] = 0.0f;
#pragma unroll
            for (int kc = 0; kc < 8; kc++) {
                uint32_t b0 = Kb[(nb * 8 + g) * KLD + kc * 8 + q];
                uint32_t b1 = Kb[(nb * 8 + g) * KLD + kc * 8 + q + 4];
                mma_tf32(sacc[nb], qa[kc], b0, b1);
            }
        }

        // ---- online softmax on registers (rows g and g+8) ----
        float mx0 = -CUDART_INF_F, mx1 = -CUDART_INF_F;
#pragma unroll
        for (int nb = 0; nb < 8; nb++) {
            mx0 = fmaxf(mx0, fmaxf(sacc[nb][0], sacc[nb][1]));
            mx1 = fmaxf(mx1, fmaxf(sacc[nb][2], sacc[nb][3]));
        }
        mx0 = fmaxf(mx0, __shfl_xor_sync(0xffffffffu, mx0, 1));
        mx0 = fmaxf(mx0, __shfl_xor_sync(0xffffffffu, mx0, 2));
        mx1 = fmaxf(mx1, __shfl_xor_sync(0xffffffffu, mx1, 1));
        mx1 = fmaxf(mx1, __shfl_xor_sync(0xffffffffu, mx1, 2));

        float mn0 = fmaxf(m0r, mx0), mn1 = fmaxf(m1r, mx1);
        float al0 = __expf(m0r - mn0), al1 = __expf(m1r - mn1);
        m0r = mn0; m1r = mn1;

        float s0 = 0.0f, s1 = 0.0f;
#pragma unroll
        for (int nb = 0; nb < 8; nb++) {
            sacc[nb][0] = __expf(sacc[nb][0] - mn0); s0 += sacc[nb][0];
            sacc[nb][1] = __expf(sacc[nb][1] - mn0); s0 += sacc[nb][1];
            sacc[nb][2] = __expf(sacc[nb][2] - mn1); s1 += sacc[nb][2];
            sacc[nb][3] = __expf(sacc[nb][3] - mn1); s1 += sacc[nb][3];
        }
        s0 += __shfl_xor_sync(0xffffffffu, s0, 1);
        s0 += __shfl_xor_sync(0xffffffffu, s0, 2);
        s1 += __shfl_xor_sync(0xffffffffu, s1, 1);
        s1 += __shfl_xor_sync(0xffffffffu, s1, 2);
        l0r = l0r * al0 + s0;
        l1r = l1r * al1 + s1;

#pragma unroll
        for (int nb = 0; nb < 8; nb++) {
            oacc[nb][0] *= al0; oacc[nb][1] *= al0;
            oacc[nb][2] *= al1; oacc[nb][3] *= al1;
        }

        // ---- O += P @ V : permute P accum layout -> A layout via shuffles ----
        const int src1 = (lane & ~3) | (q >> 1);
        const int src2 = src1 + 2;
        const bool odd = (q & 1);
#pragma unroll
        for (int kc = 0; kc < 8; kc++) {
            float e, o;
            uint32_t pa[4];
            e = __shfl_sync(0xffffffffu, sacc[kc][0], src1);
            o = __shfl_sync(0xffffffffu, sacc[kc][1], src1);
            pa[0] = f2tf32(odd ? o : e);
            e = __shfl_sync(0xffffffffu, sacc[kc][2], src1);
            o = __shfl_sync(0xffffffffu, sacc[kc][3], src1);
            pa[1] = f2tf32(odd ? o : e);
            e = __shfl_sync(0xffffffffu, sacc[kc][0], src2);
            o = __shfl_sync(0xffffffffu, sacc[kc][1], src2);
            pa[2] = f2tf32(odd ? o : e);
            e = __shfl_sync(0xffffffffu, sacc[kc][2], src2);
            o = __shfl_sync(0xffffffffu, sacc[kc][3], src2);
            pa[3] = f2tf32(odd ? o : e);
#pragma unroll
            for (int nb = 0; nb < 8; nb++) {
                uint32_t vb0 = Vb[(kc * 8 + q) * VLD + nb * 8 + g];
                uint32_t vb1 = Vb[(kc * 8 + q + 4) * VLD + nb * 8 + g];
                mma_tf32(oacc[nb], pa, vb0, vb1);
            }
        }

        __syncthreads();
        if (j + 2 < NT) FL_PREFETCH(j + 2, buf);
    }
#undef FL_PREFETCH

    // ---- normalize + write merged [b, q, h*64+d] as tf32 bits ----
    float inv0 = 1.0f / l0r, inv1 = 1.0f / l1r;
    int r0 = q0 + wid * 16 + g;
    float* og0 = g_attn + ((size_t)(b * SQ + r0) * DMODEL) + h * DHEAD;
    float* og1 = g_attn + ((size_t)(b * SQ + r0 + 8) * DMODEL) + h * DHEAD;
#pragma unroll
    for (int nb = 0; nb < 8; nb++) {
        float2 v0 = make_float2(__uint_as_float(f2tf32(oacc[nb][0] * inv0)),
                                __uint_as_float(f2tf32(oacc[nb][1] * inv0)));
        float2 v1 = make_float2(__uint_as_float(f2tf32(oacc[nb][2] * inv1)),
                                __uint_as_float(f2tf32(oacc[nb][3] * inv1)));
        *(float2*)(og0 + nb * 8 + 2 * q) = v0;
        *(float2*)(og1 + nb * 8 + 2 * q) = v1;
    }
}

// ---------------------------------------------------------------------------
// Launch
// ---------------------------------------------------------------------------
extern "C" void kernel_launch(void* const* d_in, const int* in_sizes, int n_in,
                              void* d_out, int out_size)
{
    const float* q  = (const float*)d_in[0];
    const float* k  = (const float*)d_in[1];
    const float* v  = (const float*)d_in[2];
    const float* Wq = (const float*)d_in[3];
    const float* bq = (const float*)d_in[4];
    const float* Wk = (const float*)d_in[5];
    const float* bk = (const float*)d_in[6];
    const float* Wv = (const float*)d_in[7];
    const float* bv = (const float*)d_in[8];
    const float* Wo = (const float*)d_in[9];
    const float* bo = (const float*)d_in[10];
    float* out = (float*)d_out;

    static bool attr_done = false;
    if (!attr_done) {
        cudaFuncSetAttribute(gemm_tf32_kernel<0>, cudaFuncAttributeMaxDynamicSharedMemorySize, GEMM_SMEM);
        cudaFuncSetAttribute(gemm_tf32_kernel<1>, cudaFuncAttributeMaxDynamicSharedMemorySize, GEMM_SMEM);
        cudaFuncSetAttribute(flash_attn_kernel, cudaFuncAttributeMaxDynamicSharedMemorySize, FLASH_SMEM);
        attr_done = true;
    }

    // 1. Round inputs + weights to tf32 bits (one launch)
    {
        dim3 cgrid(4096, 7);
        preconvert_kernel<<<cgrid, 256>>>((const float4*)q, (const float4*)k, (const float4*)v,
                                          (const float4*)Wq, (const float4*)Wk,
                                          (const float4*)Wv, (const float4*)Wo);
    }

    // 2. Batched Q/K/V projections -> head-major tf32 scratch
    {
        dim3 ggrid(DMODEL / 128, MROWS / 128, 3);   // (8, 32, 3)
        gemm_tf32_kernel<0><<<ggrid, 128, GEMM_SMEM>>>(bq, bk, bv, nullptr);
    }

    // 3. Flash attention
    {
        dim3 fgrid(SQ / 128, NHEADS, NBATCH);       // (16, 16, 2)
        flash_attn_kernel<<<fgrid, 256, FLASH_SMEM>>>();
    }

    // 4. Output projection
    {
        dim3 ggrid(DMODEL / 128, MROWS / 128, 1);   // (8, 32)
        gemm_tf32_kernel<1><<<ggrid, 128, GEMM_SMEM>>>(bo, nullptr, nullptr, out);
    }
}